// round 1
// baseline (speedup 1.0000x reference)
#include <cuda_runtime.h>
#include <cuda_bf16.h>
#include <math.h>

// Problem dims
#define BN_ 128      // batch
#define SN_ 1024     // sequence
#define DN_ 64       // input dim
#define HN_ 128      // hidden
#define ON_ 512      // output
#define FK_ 896      // 7*H feature dim

// Scratch (device globals: allocation-free rule)
__device__ float g_pt[(size_t)BN_ * SN_ * HN_];          // 64 MB: encoded phases
__device__ float g_feats[(size_t)BN_ * SN_ * FK_];       // 470 MB: feature matrix [B*S, 7H]
__device__ int   g_rep[SN_];                             // repeat flags per step

// ---------------------------------------------------------------------------
// Kernel 1: encoder pt[b,s,h] = sum_d x[b,s,d]*We[h,d] + be[h]
// block = 128 threads (one per h), handles 8 consecutive s for one b.
// We cached in smem with +1 padding (stride 65) to kill 32-way conflicts.
// ---------------------------------------------------------------------------
__global__ __launch_bounds__(128) void encoder_kernel(
    const float* __restrict__ x, const float* __restrict__ We,
    const float* __restrict__ be)
{
    __shared__ float sWe[HN_ * 65];
    __shared__ float sx[8 * DN_];
    int tid = threadIdx.x;

    for (int i = tid; i < HN_ * DN_; i += 128)
        sWe[(i >> 6) * 65 + (i & 63)] = We[i];

    int blk = blockIdx.x;               // 0 .. B*(S/8)-1 = 16383
    int b  = blk >> 7;                  // / (S/8=128)
    int sc = blk & 127;
    const float* xp = x + ((size_t)b * SN_ + (size_t)sc * 8) * DN_;
    for (int i = tid; i < 8 * DN_; i += 128) sx[i] = xp[i];
    __syncthreads();

    float bias = be[tid];
    float* ptp = g_pt + ((size_t)b * SN_ + (size_t)sc * 8) * HN_ + tid;
    const float* wrow = &sWe[tid * 65];
#pragma unroll
    for (int s = 0; s < 8; s++) {
        float acc = bias;
#pragma unroll
        for (int d = 0; d < DN_; d++) acc += sx[s * DN_ + d] * wrow[d];
        ptp[(size_t)s * HN_] = acc;
    }
}

// ---------------------------------------------------------------------------
// Kernel 2: repeat flags rep[s] = all(x[:,s,:] == x[:,s-1,:]); rep[0]=0
// ---------------------------------------------------------------------------
__global__ void rep_kernel(const float* __restrict__ x)
{
    int s = blockIdx.x;
    if (s == 0) { if (threadIdx.x == 0) g_rep[0] = 0; return; }
    int ok = 1;
    for (int i = threadIdx.x; i < BN_ * DN_; i += blockDim.x) {
        int b = i >> 6, d = i & 63;
        size_t base = ((size_t)b * SN_ + s) * DN_ + d;
        if (x[base] != x[base - DN_]) ok = 0;
    }
    ok = __syncthreads_and(ok);
    if (threadIdx.x == 0) g_rep[s] = ok;
}

// ---------------------------------------------------------------------------
// Kernel 3: recurrence. One thread per (b,h) chain; 1024 serial steps.
// theta only appears inside sin(), which is 2pi-periodic -> use pt directly
// (atan2 wrap is a mathematical no-op).
// Writes ph_hist, wb_hist and the 7 feature blocks (all coalesced over h).
// ---------------------------------------------------------------------------
__global__ __launch_bounds__(256) void recur_kernel(
    const float* __restrict__ omega,
    float* __restrict__ ph_hist, float* __restrict__ wb_hist)
{
    __shared__ int srep[SN_];
    int tid = threadIdx.x;
    for (int i = tid; i < SN_; i += 256) srep[i] = g_rep[i];
    __syncthreads();

    int idx = blockIdx.x * 256 + tid;   // 0..16383
    int b = idx >> 7;
    int h = idx & (HN_ - 1);
    float om = omega[h];

    float ph = 0.0f, wb = 0.0f;
    const float* pp = g_pt + (size_t)b * SN_ * HN_ + h;
    float* php = ph_hist + (size_t)b * SN_ * HN_ + h;
    float* wbp = wb_hist + (size_t)b * SN_ * HN_ + h;
    float* fp  = g_feats + (size_t)b * SN_ * FK_ + h;

    float pnext = pp[0];
    for (int t = 0; t < SN_; t++) {
        float p = pnext;
        if (t < SN_ - 1) pnext = pp[(size_t)(t + 1) * HN_];   // prefetch
        wb += 0.015625f;                                       // exact in fp32
        // ph_new = ph + omega + (-1)*sin(theta-ph) + 0.25*sin(wb)
        ph = ph + om - sinf(p - ph) + 0.25f * sinf(wb);
        if (srep[t]) wb += 0.25f * sinf(p - wb);
        php[(size_t)t * HN_] = ph;
        wbp[(size_t)t * HN_] = wb;
        float c1, s1, c2, s2, c3, s3;
        sincosf(ph, &s1, &c1);
        sincosf(0.5f * ph, &s2, &c2);
        sincosf(wb, &s3, &c3);
        float* f = fp + (size_t)t * FK_;
        f[0 * HN_] = c1; f[1 * HN_] = s1;
        f[2 * HN_] = c2; f[3 * HN_] = s2;
        f[4 * HN_] = c3; f[5 * HN_] = s3;
        f[6 * HN_] = ph;
    }
}

// ---------------------------------------------------------------------------
// Kernel 4: readout GEMM  C[m,o] = sum_k feats[m,k] * Wr[o,k] + br[o]
// M=131072, N=512, K=896. Classic 128x128x16 SGEMM, 256 threads, 8x8
// microtiles in split-4 layout (conflict-free LDS.128 on both operands).
// ---------------------------------------------------------------------------
__global__ __launch_bounds__(256) void readout_gemm(
    const float* __restrict__ W, const float* __restrict__ br,
    float* __restrict__ C)
{
    const int K = FK_, N = ON_;
    __shared__ float As[16][128];
    __shared__ float Bs[16][128];

    int tid = threadIdx.x;
    size_t bm = (size_t)blockIdx.x * 128;
    int bn = blockIdx.y * 128;

    int lr = tid >> 2;              // 0..63
    int lc = (tid & 3) << 2;        // 0,4,8,12
    const float* Ag = g_feats + (bm + lr) * (size_t)K + lc;
    const float* Wg = W + (size_t)(bn + lr) * K + lc;

    int tx = tid & 15, ty = tid >> 4;
    float acc[8][8];
#pragma unroll
    for (int i = 0; i < 8; i++)
#pragma unroll
        for (int j = 0; j < 8; j++) acc[i][j] = 0.0f;

    for (int k0 = 0; k0 < K; k0 += 16) {
        float4 a0 = *(const float4*)(Ag + k0);
        float4 a1 = *(const float4*)(Ag + (size_t)64 * K + k0);
        float4 b0 = *(const float4*)(Wg + k0);
        float4 b1 = *(const float4*)(Wg + (size_t)64 * K + k0);
        __syncthreads();
        As[lc + 0][lr] = a0.x; As[lc + 1][lr] = a0.y;
        As[lc + 2][lr] = a0.z; As[lc + 3][lr] = a0.w;
        As[lc + 0][lr + 64] = a1.x; As[lc + 1][lr + 64] = a1.y;
        As[lc + 2][lr + 64] = a1.z; As[lc + 3][lr + 64] = a1.w;
        Bs[lc + 0][lr] = b0.x; Bs[lc + 1][lr] = b0.y;
        Bs[lc + 2][lr] = b0.z; Bs[lc + 3][lr] = b0.w;
        Bs[lc + 0][lr + 64] = b1.x; Bs[lc + 1][lr + 64] = b1.y;
        Bs[lc + 2][lr + 64] = b1.z; Bs[lc + 3][lr + 64] = b1.w;
        __syncthreads();
#pragma unroll
        for (int k = 0; k < 16; k++) {
            float ar[8], bb[8];
            *(float4*)(ar)     = *(const float4*)&As[k][ty * 4];
            *(float4*)(ar + 4) = *(const float4*)&As[k][64 + ty * 4];
            *(float4*)(bb)     = *(const float4*)&Bs[k][tx * 4];
            *(float4*)(bb + 4) = *(const float4*)&Bs[k][64 + tx * 4];
#pragma unroll
            for (int i = 0; i < 8; i++)
#pragma unroll
                for (int j = 0; j < 8; j++) acc[i][j] += ar[i] * bb[j];
        }
    }

    // epilogue: rows {ty*4..+3, 64+ty*4..+3}, cols {tx*4..+3, 64+tx*4..+3}
    float4 brv0 = *(const float4*)(br + bn + tx * 4);
    float4 brv1 = *(const float4*)(br + bn + 64 + tx * 4);
#pragma unroll
    for (int i = 0; i < 8; i++) {
        int row = (i < 4) ? (ty * 4 + i) : (64 + ty * 4 + (i - 4));
        float* Crow = C + (bm + row) * (size_t)N + bn;
        float4 v0, v1;
        v0.x = acc[i][0] + brv0.x; v0.y = acc[i][1] + brv0.y;
        v0.z = acc[i][2] + brv0.z; v0.w = acc[i][3] + brv0.w;
        v1.x = acc[i][4] + brv1.x; v1.y = acc[i][5] + brv1.y;
        v1.z = acc[i][6] + brv1.z; v1.w = acc[i][7] + brv1.w;
        *(float4*)(Crow + tx * 4)      = v0;
        *(float4*)(Crow + 64 + tx * 4) = v1;
    }
}

// ---------------------------------------------------------------------------
extern "C" void kernel_launch(void* const* d_in, const int* in_sizes, int n_in,
                              void* d_out, int out_size)
{
    const float* x     = (const float*)d_in[0];  // [B,S,D]
    const float* We    = (const float*)d_in[1];  // [H,D]
    const float* be    = (const float*)d_in[2];  // [H]
    const float* omega = (const float*)d_in[3];  // [H]
    const float* Wr    = (const float*)d_in[4];  // [O,7H]
    const float* br    = (const float*)d_in[5];  // [O]

    float* out     = (float*)d_out;
    float* logits  = out;                                          // [B,S,O]
    float* ph_hist = out + (size_t)BN_ * SN_ * ON_;                // [B,S,H]
    float* wb_hist = ph_hist + (size_t)BN_ * SN_ * HN_;            // [B,S,H]

    encoder_kernel<<<BN_ * (SN_ / 8), 128>>>(x, We, be);
    rep_kernel<<<SN_, 256>>>(x);
    recur_kernel<<<(BN_ * HN_) / 256, 256>>>(omega, ph_hist, wb_hist);
    readout_gemm<<<dim3((BN_ * SN_) / 128, ON_ / 128), 256>>>(Wr, br, logits);
}

// round 4
// speedup vs baseline: 3.1609x; 3.1609x over previous
#include <cuda_runtime.h>
#include <cuda_bf16.h>
#include <cuda_fp16.h>
#include <math.h>
#include <stdint.h>

// Problem dims
#define BN_ 128
#define SN_ 1024
#define DN_ 64
#define HN_ 128
#define ON_ 512
#define FK_ 896
#define MTOT_ (BN_ * SN_)   // 131072

// ---------------------------------------------------------------------------
// Scratch (device globals: allocation-free rule)
// ---------------------------------------------------------------------------
__device__ float  g_pt[(size_t)MTOT_ * HN_];     // 64 MB encoded phases
__device__ __half g_f[(size_t)MTOT_ * FK_];      // 235 MB feats fp16
__device__ __half g_w[(size_t)ON_ * FK_];        // Wr fp16
__device__ int    g_rep[SN_];

__device__ __forceinline__ uint32_t smem_u32(const void* p) {
    uint32_t a;
    asm("{ .reg .u64 t; cvta.to.shared.u64 t, %1; cvt.u32.u64 %0, t; }" : "=r"(a) : "l"(p));
    return a;
}
__device__ __forceinline__ void cp16(uint32_t dst, const void* src) {
    asm volatile("cp.async.cg.shared.global [%0], [%1], 16;" :: "r"(dst), "l"(src));
}
#define CP_COMMIT() asm volatile("cp.async.commit_group;" ::: "memory")
#define CP_WAIT(n)  asm volatile("cp.async.wait_group %0;" :: "n"(n) : "memory")
#define SWZ(o) ((o) ^ (((o) >> 3) & 0x70))

__device__ __forceinline__ void ldm4(uint32_t* r, uint32_t addr) {
    asm volatile("ldmatrix.sync.aligned.m8n8.x4.shared.b16 {%0,%1,%2,%3}, [%4];"
        : "=r"(r[0]), "=r"(r[1]), "=r"(r[2]), "=r"(r[3]) : "r"(addr));
}
__device__ __forceinline__ void mma16816(float* d, const uint32_t* a, const uint32_t* b) {
    asm volatile("mma.sync.aligned.m16n8k16.row.col.f32.f16.f16.f32 "
        "{%0,%1,%2,%3}, {%4,%5,%6,%7}, {%8,%9}, {%0,%1,%2,%3};"
        : "+f"(d[0]), "+f"(d[1]), "+f"(d[2]), "+f"(d[3])
        : "r"(a[0]), "r"(a[1]), "r"(a[2]), "r"(a[3]), "r"(b[0]), "r"(b[1]));
}

// ---------------------------------------------------------------------------
// Kernel 1: encoder pt[b,s,h] = x[b,s,:] @ We[h,:] + be[h]
// ---------------------------------------------------------------------------
__global__ __launch_bounds__(128) void encoder_kernel(
    const float* __restrict__ x, const float* __restrict__ We,
    const float* __restrict__ be)
{
    __shared__ float sWe[HN_ * 65];
    __shared__ float sx[8 * DN_];
    int tid = threadIdx.x;
    for (int i = tid; i < HN_ * DN_; i += 128)
        sWe[(i >> 6) * 65 + (i & 63)] = We[i];
    int blk = blockIdx.x;
    int b = blk >> 7, sc = blk & 127;
    const float* xp = x + ((size_t)b * SN_ + (size_t)sc * 8) * DN_;
    for (int i = tid; i < 8 * DN_; i += 128) sx[i] = xp[i];
    __syncthreads();
    float bias = be[tid];
    float* ptp = g_pt + ((size_t)b * SN_ + (size_t)sc * 8) * HN_ + tid;
    const float* wrow = &sWe[tid * 65];
#pragma unroll
    for (int s = 0; s < 8; s++) {
        float acc = bias;
#pragma unroll
        for (int d = 0; d < DN_; d++) acc += sx[s * DN_ + d] * wrow[d];
        ptp[(size_t)s * HN_] = acc;
    }
}

// ---------------------------------------------------------------------------
// Kernel 2: repeat flags
// ---------------------------------------------------------------------------
__global__ void rep_kernel(const float* __restrict__ x)
{
    int s = blockIdx.x;
    if (s == 0) { if (threadIdx.x == 0) g_rep[0] = 0; return; }
    int ok = 1;
    for (int i = threadIdx.x; i < BN_ * DN_; i += blockDim.x) {
        int b = i >> 6, d = i & 63;
        size_t base = ((size_t)b * SN_ + s) * DN_ + d;
        if (x[base] != x[base - DN_]) ok = 0;
    }
    ok = __syncthreads_and(ok);
    if (threadIdx.x == 0) g_rep[s] = ok;
}

// ---------------------------------------------------------------------------
// Kernel 3: recurrence state only (2 sinf on the serial critical path)
// ---------------------------------------------------------------------------
__global__ __launch_bounds__(256) void recur_state(
    const float* __restrict__ omega,
    float* __restrict__ ph_hist, float* __restrict__ wb_hist)
{
    __shared__ int srep[SN_];
    int tid = threadIdx.x;
    for (int i = tid; i < SN_; i += 256) srep[i] = g_rep[i];
    __syncthreads();

    int idx = blockIdx.x * 256 + tid;
    int b = idx >> 7, h = idx & (HN_ - 1);
    float om = omega[h];
    float ph = 0.0f, wb = 0.0f;
    const float* pp = g_pt + (size_t)b * SN_ * HN_ + h;
    float* php = ph_hist + (size_t)b * SN_ * HN_ + h;
    float* wbp = wb_hist + (size_t)b * SN_ * HN_ + h;

    float pnext = pp[0];
    for (int t = 0; t < SN_; t++) {
        float p = pnext;
        if (t < SN_ - 1) pnext = pp[(size_t)(t + 1) * HN_];
        wb += 0.015625f;
        ph = ph + om - sinf(p - ph) + 0.25f * sinf(wb);
        if (srep[t]) wb += 0.25f * sinf(p - wb);
        php[(size_t)t * HN_] = ph;
        wbp[(size_t)t * HN_] = wb;
    }
}

// ---------------------------------------------------------------------------
// Kernel 4: featurize — each thread handles 2 adjacent h, writes __half2
// feats [M, 7H]: cos ph | sin ph | cos ph/2 | sin ph/2 | cos wb | sin wb | ph
// ---------------------------------------------------------------------------
__global__ __launch_bounds__(256) void featurize(
    const float* __restrict__ ph_hist, const float* __restrict__ wb_hist)
{
    size_t gid = (size_t)blockIdx.x * 256 + threadIdx.x;   // over M*H/2
    size_t m = gid >> 6;
    int h = (int)(gid & 63) * 2;
    float2 ph = *(const float2*)(ph_hist + m * HN_ + h);
    float2 wb = *(const float2*)(wb_hist + m * HN_ + h);
    float c1a, s1a, c2a, s2a, c3a, s3a, c1b, s1b, c2b, s2b, c3b, s3b;
    sincosf(ph.x, &s1a, &c1a); sincosf(ph.y, &s1b, &c1b);
    sincosf(0.5f * ph.x, &s2a, &c2a); sincosf(0.5f * ph.y, &s2b, &c2b);
    sincosf(wb.x, &s3a, &c3a); sincosf(wb.y, &s3b, &c3b);
    __half2* f = (__half2*)(g_f + m * FK_ + h);
    f[0 * HN_ / 2] = __floats2half2_rn(c1a, c1b);
    f[1 * HN_ / 2] = __floats2half2_rn(s1a, s1b);
    f[2 * HN_ / 2] = __floats2half2_rn(c2a, c2b);
    f[3 * HN_ / 2] = __floats2half2_rn(s2a, s2b);
    f[4 * HN_ / 2] = __floats2half2_rn(c3a, c3b);
    f[5 * HN_ / 2] = __floats2half2_rn(s3a, s3b);
    f[6 * HN_ / 2] = __floats2half2_rn(ph.x, ph.y);
}

// ---------------------------------------------------------------------------
// Kernel 5: Wr -> fp16
// ---------------------------------------------------------------------------
__global__ __launch_bounds__(256) void wconv(const float* __restrict__ Wr)
{
    size_t i = (size_t)blockIdx.x * 256 + threadIdx.x;
    if (i < (size_t)ON_ * FK_) g_w[i] = __float2half(Wr[i]);
}

// ---------------------------------------------------------------------------
// Kernel 6: HMMA GEMM  C[m,o] = feats[m,:] . Wr[o,:] + br[o]
// CTA 128x128, K chunks of 64 fp16 (128B SW128 rows), cp.async double buffer.
// 8 warps: 4 along M x 2 along N; warp tile 32x64 via m16n8k16.
// ---------------------------------------------------------------------------
#define ASZ   16384
#define STAGE 32768
#define GEMM_SMEM (2 * STAGE + 1024)
#define NCHUNK 14

__global__ __launch_bounds__(256) void gemm_hmma(
    const float* __restrict__ br, float* __restrict__ C)
{
    extern __shared__ char smem[];
    uint32_t sb = (smem_u32(smem) + 1023) & ~1023u;
    int tid = threadIdx.x;
    int lane = tid & 31, wid = tid >> 5;
    int warpM = wid & 3, warpN = wid >> 2;
    int bn = blockIdx.x * 128;                 // N tile (0..3)
    size_t bm = (size_t)blockIdx.y * 128;      // M tile

    const __half* Ab = g_f + bm * FK_;
    const __half* Bb = g_w + (size_t)bn * FK_;

    auto load_chunk = [&](int c) {
        uint32_t stb = sb + (c & 1) * STAGE;
        int k0 = c * 64;
#pragma unroll
        for (int u = tid; u < 1024; u += 256) {
            int row = u >> 3, sg = (u & 7) * 16;
            uint32_t off = SWZ(row * 128 + sg);
            cp16(stb + off, (const char*)(Ab + (size_t)row * FK_ + k0) + sg);
            cp16(stb + ASZ + off, (const char*)(Bb + (size_t)row * FK_ + k0) + sg);
        }
    };

    float acc[2][8][4];
#pragma unroll
    for (int mt = 0; mt < 2; mt++)
#pragma unroll
        for (int f = 0; f < 8; f++)
#pragma unroll
            for (int j = 0; j < 4; j++) acc[mt][f][j] = 0.0f;

    // fragment smem address bases (per-lane, constant over chunks)
    int aRow = warpM * 32 + (lane & 15);
    int aK8  = (lane >> 4);                        // 0/1 -> +8 halves
    int bNr  = warpN * 64 + ((lane >> 4) << 3) + (lane & 7);
    int bK8  = (lane >> 3) & 1;

    load_chunk(0);
    CP_COMMIT();

    for (int c = 0; c < NCHUNK; c++) {
        if (c + 1 < NCHUNK) { load_chunk(c + 1); CP_COMMIT(); CP_WAIT(1); }
        else                { CP_WAIT(0); }
        __syncthreads();
        uint32_t stb = sb + (c & 1) * STAGE;
#pragma unroll
        for (int kk = 0; kk < 4; kk++) {
            uint32_t a[2][4], b[4][4];
#pragma unroll
            for (int mt = 0; mt < 2; mt++) {
                int khalf = kk * 16 + aK8 * 8;
                ldm4(a[mt], stb + SWZ((aRow + mt * 16) * 128 + khalf * 2));
            }
#pragma unroll
            for (int np = 0; np < 4; np++) {
                int khalf = kk * 16 + bK8 * 8;
                ldm4(b[np], stb + ASZ + SWZ((bNr + np * 16) * 128 + khalf * 2));
            }
#pragma unroll
            for (int mt = 0; mt < 2; mt++)
#pragma unroll
                for (int np = 0; np < 4; np++) {
                    mma16816(acc[mt][np * 2 + 0], a[mt], &b[np][0]);
                    mma16816(acc[mt][np * 2 + 1], a[mt], &b[np][2]);
                }
        }
        __syncthreads();
    }

    // epilogue
    int g = lane >> 2, t = lane & 3;
#pragma unroll
    for (int f = 0; f < 8; f++) {
        int col = bn + warpN * 64 + f * 8 + 2 * t;
        float2 bv = *(const float2*)(br + col);
#pragma unroll
        for (int mt = 0; mt < 2; mt++) {
            int r0 = warpM * 32 + mt * 16 + g;
            float* c0 = C + (bm + r0) * (size_t)ON_ + col;
            float* c1 = C + (bm + r0 + 8) * (size_t)ON_ + col;
            float2 v0 = { acc[mt][f][0] + bv.x, acc[mt][f][1] + bv.y };
            float2 v1 = { acc[mt][f][2] + bv.x, acc[mt][f][3] + bv.y };
            *(float2*)c0 = v0;
            *(float2*)c1 = v1;
        }
    }
}

// ---------------------------------------------------------------------------
extern "C" void kernel_launch(void* const* d_in, const int* in_sizes, int n_in,
                              void* d_out, int out_size)
{
    const float* x     = (const float*)d_in[0];
    const float* We    = (const float*)d_in[1];
    const float* be    = (const float*)d_in[2];
    const float* omega = (const float*)d_in[3];
    const float* Wr    = (const float*)d_in[4];
    const float* br    = (const float*)d_in[5];

    float* out     = (float*)d_out;
    float* logits  = out;                                   // [B,S,O]
    float* ph_hist = out + (size_t)MTOT_ * ON_;             // [B,S,H]
    float* wb_hist = ph_hist + (size_t)MTOT_ * HN_;         // [B,S,H]

    cudaFuncSetAttribute(gemm_hmma, cudaFuncAttributeMaxDynamicSharedMemorySize, GEMM_SMEM);

    encoder_kernel<<<BN_ * (SN_ / 8), 128>>>(x, We, be);
    rep_kernel<<<SN_, 256>>>(x);
    recur_state<<<(BN_ * HN_) / 256, 256>>>(omega, ph_hist, wb_hist);
    featurize<<<(MTOT_ * HN_ / 2) / 256, 256>>>(ph_hist, wb_hist);
    wconv<<<(ON_ * FK_ + 255) / 256, 256>>>(Wr);
    gemm_hmma<<<dim3(4, 1024), 256, GEMM_SMEM>>>(br, logits);
}

// round 5
// speedup vs baseline: 4.1421x; 1.3104x over previous
#include <cuda_runtime.h>
#include <cuda_bf16.h>
#include <cuda_fp16.h>
#include <math.h>
#include <stdint.h>

// Problem dims
#define BN_ 128
#define SN_ 1024
#define DN_ 64
#define HN_ 128
#define ON_ 512
#define FK_ 896
#define MTOT_ (BN_ * SN_)   // 131072

// ---------------------------------------------------------------------------
// Scratch (device globals: allocation-free rule)
// ---------------------------------------------------------------------------
__device__ float  g_pt[(size_t)MTOT_ * HN_];     // 64 MB encoded phases
__device__ __half g_f[(size_t)MTOT_ * FK_];      // 235 MB feats fp16
__device__ __half g_w[(size_t)ON_ * FK_];        // Wr fp16
__device__ int    g_rep[SN_];

__device__ __forceinline__ uint32_t smem_u32(const void* p) {
    uint32_t a;
    asm("{ .reg .u64 t; cvta.to.shared.u64 t, %1; cvt.u32.u64 %0, t; }" : "=r"(a) : "l"(p));
    return a;
}
__device__ __forceinline__ void cp16(uint32_t dst, const void* src) {
    asm volatile("cp.async.cg.shared.global [%0], [%1], 16;" :: "r"(dst), "l"(src));
}
#define CP_COMMIT() asm volatile("cp.async.commit_group;" ::: "memory")
#define CP_WAIT(n)  asm volatile("cp.async.wait_group %0;" :: "n"(n) : "memory")
#define SWZ(o) ((o) ^ (((o) >> 3) & 0x70))

__device__ __forceinline__ void ldm4(uint32_t* r, uint32_t addr) {
    asm volatile("ldmatrix.sync.aligned.m8n8.x4.shared.b16 {%0,%1,%2,%3}, [%4];"
        : "=r"(r[0]), "=r"(r[1]), "=r"(r[2]), "=r"(r[3]) : "r"(addr));
}
__device__ __forceinline__ void mma16816(float* d, const uint32_t* a, const uint32_t* b) {
    asm volatile("mma.sync.aligned.m16n8k16.row.col.f32.f16.f16.f32 "
        "{%0,%1,%2,%3}, {%4,%5,%6,%7}, {%8,%9}, {%0,%1,%2,%3};"
        : "+f"(d[0]), "+f"(d[1]), "+f"(d[2]), "+f"(d[3])
        : "r"(a[0]), "r"(a[1]), "r"(a[2]), "r"(a[3]), "r"(b[0]), "r"(b[1]));
}

// ---------------------------------------------------------------------------
// Kernel 1: encoder pt[b,s,h] = x[b,s,:] @ We[h,:] + be[h]  (fp32: feeds the
// sensitive recurrence; keep exact)
// ---------------------------------------------------------------------------
__global__ __launch_bounds__(128) void encoder_kernel(
    const float* __restrict__ x, const float* __restrict__ We,
    const float* __restrict__ be)
{
    __shared__ float sWe[HN_ * 65];
    __shared__ float sx[8 * DN_];
    int tid = threadIdx.x;
    for (int i = tid; i < HN_ * DN_; i += 128)
        sWe[(i >> 6) * 65 + (i & 63)] = We[i];
    int blk = blockIdx.x;
    int b = blk >> 7, sc = blk & 127;
    const float* xp = x + ((size_t)b * SN_ + (size_t)sc * 8) * DN_;
    for (int i = tid; i < 8 * DN_; i += 128) sx[i] = xp[i];
    __syncthreads();
    float bias = be[tid];
    float* ptp = g_pt + ((size_t)b * SN_ + (size_t)sc * 8) * HN_ + tid;
    const float* wrow = &sWe[tid * 65];
#pragma unroll
    for (int s = 0; s < 8; s++) {
        float acc = bias;
#pragma unroll
        for (int d = 0; d < DN_; d++) acc += sx[s * DN_ + d] * wrow[d];
        ptp[(size_t)s * HN_] = acc;
    }
}

// ---------------------------------------------------------------------------
// Kernel 2: repeat flags
// ---------------------------------------------------------------------------
__global__ void rep_kernel(const float* __restrict__ x)
{
    int s = blockIdx.x;
    if (s == 0) { if (threadIdx.x == 0) g_rep[0] = 0; return; }
    int ok = 1;
    for (int i = threadIdx.x; i < BN_ * DN_; i += blockDim.x) {
        int b = i >> 6, d = i & 63;
        size_t base = ((size_t)b * SN_ + s) * DN_ + d;
        if (x[base] != x[base - DN_]) ok = 0;
    }
    ok = __syncthreads_and(ok);
    if (threadIdx.x == 0) g_rep[s] = ok;
}

// ---------------------------------------------------------------------------
// Kernel 3: recurrence. __sinf on the serial critical path (25-cyc dep chain
// vs ~60 for the precise poly). Dynamics are contracting (E[log|1+cos|]<0),
// so the ~3e-5 per-step trig error does not accumulate.
// ---------------------------------------------------------------------------
__global__ __launch_bounds__(256) void recur_state(
    const float* __restrict__ omega,
    float* __restrict__ ph_hist, float* __restrict__ wb_hist)
{
    __shared__ int srep[SN_];
    int tid = threadIdx.x;
    for (int i = tid; i < SN_; i += 256) srep[i] = g_rep[i];
    __syncthreads();

    int idx = blockIdx.x * 256 + tid;
    int b = idx >> 7, h = idx & (HN_ - 1);
    float om = omega[h];
    float ph = 0.0f, wb = 0.0f;
    const float* pp = g_pt + (size_t)b * SN_ * HN_ + h;
    float* php = ph_hist + (size_t)b * SN_ * HN_ + h;
    float* wbp = wb_hist + (size_t)b * SN_ * HN_ + h;

    float pnext = pp[0];
    for (int t = 0; t < SN_; t++) {
        float p = pnext;
        if (t < SN_ - 1) pnext = pp[(size_t)(t + 1) * HN_];
        wb += 0.015625f;
        float drive = om + 0.25f * __sinf(wb);   // off the ph-critical path
        ph = ph + drive - __sinf(p - ph);
        if (srep[t]) wb += 0.25f * __sinf(p - wb);
        php[(size_t)t * HN_] = ph;
        wbp[(size_t)t * HN_] = wb;
    }
}

// ---------------------------------------------------------------------------
// Kernel 4: featurize — 2 adjacent h per thread, __half2 stores, fast trig
// feats [M, 7H]: cos ph | sin ph | cos ph/2 | sin ph/2 | cos wb | sin wb | ph
// ---------------------------------------------------------------------------
__global__ __launch_bounds__(256) void featurize(
    const float* __restrict__ ph_hist, const float* __restrict__ wb_hist)
{
    size_t gid = (size_t)blockIdx.x * 256 + threadIdx.x;   // over M*H/2
    size_t m = gid >> 6;
    int h = (int)(gid & 63) * 2;
    float2 ph = *(const float2*)(ph_hist + m * HN_ + h);
    float2 wb = *(const float2*)(wb_hist + m * HN_ + h);
    float c1a, s1a, c2a, s2a, c3a, s3a, c1b, s1b, c2b, s2b, c3b, s3b;
    __sincosf(ph.x, &s1a, &c1a); __sincosf(ph.y, &s1b, &c1b);
    __sincosf(0.5f * ph.x, &s2a, &c2a); __sincosf(0.5f * ph.y, &s2b, &c2b);
    __sincosf(wb.x, &s3a, &c3a); __sincosf(wb.y, &s3b, &c3b);
    __half2* f = (__half2*)(g_f + m * FK_ + h);
    f[0 * HN_ / 2] = __floats2half2_rn(c1a, c1b);
    f[1 * HN_ / 2] = __floats2half2_rn(s1a, s1b);
    f[2 * HN_ / 2] = __floats2half2_rn(c2a, c2b);
    f[3 * HN_ / 2] = __floats2half2_rn(s2a, s2b);
    f[4 * HN_ / 2] = __floats2half2_rn(c3a, c3b);
    f[5 * HN_ / 2] = __floats2half2_rn(s3a, s3b);
    f[6 * HN_ / 2] = __floats2half2_rn(ph.x, ph.y);
}

// ---------------------------------------------------------------------------
// Kernel 5: Wr -> fp16
// ---------------------------------------------------------------------------
__global__ __launch_bounds__(256) void wconv(const float* __restrict__ Wr)
{
    size_t i = (size_t)blockIdx.x * 256 + threadIdx.x;
    if (i < (size_t)ON_ * FK_) g_w[i] = __float2half(Wr[i]);
}

// ---------------------------------------------------------------------------
// Kernel 6: HMMA GEMM  C[m,o] = feats[m,:] . Wr[o,:] + br[o]
// CTA 128x128, K chunks of 64 fp16 (128B SW128 rows).
// 3-stage cp.async pipeline, ONE __syncthreads per chunk (3 stages make the
// stage-(c-1) WAR hazard covered by the top-of-iteration barrier).
// 8 warps: 4 along M x 2 along N; warp tile 32x64 via m16n8k16.
// ---------------------------------------------------------------------------
#define ASZ   16384
#define STAGE 32768
#define GEMM_SMEM (3 * STAGE + 1024)
#define NCHUNK 14

__global__ __launch_bounds__(256, 2) void gemm_hmma(
    const float* __restrict__ br, float* __restrict__ C)
{
    extern __shared__ char smem[];
    uint32_t sb = (smem_u32(smem) + 1023) & ~1023u;
    int tid = threadIdx.x;
    int lane = tid & 31, wid = tid >> 5;
    int warpM = wid & 3, warpN = wid >> 2;
    int bn = blockIdx.x * 128;                 // N tile (0..3)
    size_t bm = (size_t)blockIdx.y * 128;      // M tile

    const __half* Ab = g_f + bm * FK_;
    const __half* Bb = g_w + (size_t)bn * FK_;

    auto load_chunk = [&](int c) {
        uint32_t stb = sb + (c % 3) * STAGE;
        int k0 = c * 64;
#pragma unroll
        for (int u = tid; u < 1024; u += 256) {
            int row = u >> 3, sg = (u & 7) * 16;
            uint32_t off = SWZ(row * 128 + sg);
            cp16(stb + off, (const char*)(Ab + (size_t)row * FK_ + k0) + sg);
            cp16(stb + ASZ + off, (const char*)(Bb + (size_t)row * FK_ + k0) + sg);
        }
    };

    float acc[2][8][4];
#pragma unroll
    for (int mt = 0; mt < 2; mt++)
#pragma unroll
        for (int f = 0; f < 8; f++)
#pragma unroll
            for (int j = 0; j < 4; j++) acc[mt][f][j] = 0.0f;

    int aRow = warpM * 32 + (lane & 15);
    int aK8  = (lane >> 4);
    int bNr  = warpN * 64 + ((lane >> 4) << 3) + (lane & 7);
    int bK8  = (lane >> 3) & 1;

    load_chunk(0); CP_COMMIT();
    load_chunk(1); CP_COMMIT();

    for (int c = 0; c < NCHUNK; c++) {
        if (c + 1 < NCHUNK) { CP_WAIT(1); } else { CP_WAIT(0); }
        __syncthreads();
        uint32_t stb = sb + (c % 3) * STAGE;
#pragma unroll
        for (int kk = 0; kk < 4; kk++) {
            uint32_t a[2][4], b[4][4];
#pragma unroll
            for (int mt = 0; mt < 2; mt++) {
                int khalf = kk * 16 + aK8 * 8;
                ldm4(a[mt], stb + SWZ((aRow + mt * 16) * 128 + khalf * 2));
            }
#pragma unroll
            for (int np = 0; np < 4; np++) {
                int khalf = kk * 16 + bK8 * 8;
                ldm4(b[np], stb + ASZ + SWZ((bNr + np * 16) * 128 + khalf * 2));
            }
#pragma unroll
            for (int mt = 0; mt < 2; mt++)
#pragma unroll
                for (int np = 0; np < 4; np++) {
                    mma16816(acc[mt][np * 2 + 0], a[mt], &b[np][0]);
                    mma16816(acc[mt][np * 2 + 1], a[mt], &b[np][2]);
                }
        }
        if (c + 2 < NCHUNK) { load_chunk(c + 2); CP_COMMIT(); }
    }

    // epilogue
    int g = lane >> 2, t = lane & 3;
#pragma unroll
    for (int f = 0; f < 8; f++) {
        int col = bn + warpN * 64 + f * 8 + 2 * t;
        float2 bv = *(const float2*)(br + col);
#pragma unroll
        for (int mt = 0; mt < 2; mt++) {
            int r0 = warpM * 32 + mt * 16 + g;
            float* c0 = C + (bm + r0) * (size_t)ON_ + col;
            float* c1 = C + (bm + r0 + 8) * (size_t)ON_ + col;
            float2 v0 = { acc[mt][f][0] + bv.x, acc[mt][f][1] + bv.y };
            float2 v1 = { acc[mt][f][2] + bv.x, acc[mt][f][3] + bv.y };
            *(float2*)c0 = v0;
            *(float2*)c1 = v1;
        }
    }
}

// ---------------------------------------------------------------------------
extern "C" void kernel_launch(void* const* d_in, const int* in_sizes, int n_in,
                              void* d_out, int out_size)
{
    const float* x     = (const float*)d_in[0];
    const float* We    = (const float*)d_in[1];
    const float* be    = (const float*)d_in[2];
    const float* omega = (const float*)d_in[3];
    const float* Wr    = (const float*)d_in[4];
    const float* br    = (const float*)d_in[5];

    float* out     = (float*)d_out;
    float* logits  = out;                                   // [B,S,O]
    float* ph_hist = out + (size_t)MTOT_ * ON_;             // [B,S,H]
    float* wb_hist = ph_hist + (size_t)MTOT_ * HN_;         // [B,S,H]

    cudaFuncSetAttribute(gemm_hmma, cudaFuncAttributeMaxDynamicSharedMemorySize, GEMM_SMEM);

    encoder_kernel<<<BN_ * (SN_ / 8), 128>>>(x, We, be);
    rep_kernel<<<SN_, 256>>>(x);
    recur_state<<<(BN_ * HN_) / 256, 256>>>(omega, ph_hist, wb_hist);
    featurize<<<(MTOT_ * HN_ / 2) / 256, 256>>>(ph_hist, wb_hist);
    wconv<<<(ON_ * FK_ + 255) / 256, 256>>>(Wr);
    gemm_hmma<<<dim3(4, 1024), 256, GEMM_SMEM>>>(br, logits);
}

// round 6
// speedup vs baseline: 4.1593x; 1.0042x over previous
#include <cuda_runtime.h>
#include <cuda_bf16.h>
#include <cuda_fp16.h>
#include <math.h>
#include <stdint.h>

// Problem dims
#define BN_ 128
#define SN_ 1024
#define DN_ 64
#define HN_ 128
#define ON_ 512
#define FK_ 896
#define MTOT_ (BN_ * SN_)   // 131072

// ---------------------------------------------------------------------------
// Scratch (device globals: allocation-free rule)
// ---------------------------------------------------------------------------
__device__ float  g_pt[(size_t)MTOT_ * HN_];     // 64 MB encoded phases
__device__ __half g_f[(size_t)MTOT_ * FK_];      // 235 MB feats fp16
__device__ __half g_w[(size_t)ON_ * FK_];        // Wr fp16
__device__ int    g_rep[SN_];

__device__ __forceinline__ uint32_t smem_u32(const void* p) {
    uint32_t a;
    asm("{ .reg .u64 t; cvta.to.shared.u64 t, %1; cvt.u32.u64 %0, t; }" : "=r"(a) : "l"(p));
    return a;
}
__device__ __forceinline__ void cp16(uint32_t dst, const void* src) {
    asm volatile("cp.async.cg.shared.global [%0], [%1], 16;" :: "r"(dst), "l"(src));
}
#define CP_COMMIT() asm volatile("cp.async.commit_group;" ::: "memory")
#define CP_WAIT(n)  asm volatile("cp.async.wait_group %0;" :: "n"(n) : "memory")
#define SWZ(o) ((o) ^ (((o) >> 3) & 0x70))

__device__ __forceinline__ void ldm4(uint32_t* r, uint32_t addr) {
    asm volatile("ldmatrix.sync.aligned.m8n8.x4.shared.b16 {%0,%1,%2,%3}, [%4];"
        : "=r"(r[0]), "=r"(r[1]), "=r"(r[2]), "=r"(r[3]) : "r"(addr));
}
__device__ __forceinline__ void mma16816(float* d, const uint32_t* a, const uint32_t* b) {
    asm volatile("mma.sync.aligned.m16n8k16.row.col.f32.f16.f16.f32 "
        "{%0,%1,%2,%3}, {%4,%5,%6,%7}, {%8,%9}, {%0,%1,%2,%3};"
        : "+f"(d[0]), "+f"(d[1]), "+f"(d[2]), "+f"(d[3])
        : "r"(a[0]), "r"(a[1]), "r"(a[2]), "r"(a[3]), "r"(b[0]), "r"(b[1]));
}

// ---------------------------------------------------------------------------
// Kernel 1: encoder pt[b,s,h] = x[b,s,:] @ We[h,:] + be[h]  (fp32: feeds the
// sensitive recurrence; keep exact)
// ---------------------------------------------------------------------------
__global__ __launch_bounds__(128) void encoder_kernel(
    const float* __restrict__ x, const float* __restrict__ We,
    const float* __restrict__ be)
{
    __shared__ float sWe[HN_ * 65];
    __shared__ float sx[8 * DN_];
    int tid = threadIdx.x;
    for (int i = tid; i < HN_ * DN_; i += 128)
        sWe[(i >> 6) * 65 + (i & 63)] = We[i];
    int blk = blockIdx.x;
    int b = blk >> 7, sc = blk & 127;
    const float* xp = x + ((size_t)b * SN_ + (size_t)sc * 8) * DN_;
    for (int i = tid; i < 8 * DN_; i += 128) sx[i] = xp[i];
    __syncthreads();
    float bias = be[tid];
    float* ptp = g_pt + ((size_t)b * SN_ + (size_t)sc * 8) * HN_ + tid;
    const float* wrow = &sWe[tid * 65];
#pragma unroll
    for (int s = 0; s < 8; s++) {
        float acc = bias;
#pragma unroll
        for (int d = 0; d < DN_; d++) acc += sx[s * DN_ + d] * wrow[d];
        ptp[(size_t)s * HN_] = acc;
    }
}

// ---------------------------------------------------------------------------
// Kernel 2: repeat flags
// ---------------------------------------------------------------------------
__global__ void rep_kernel(const float* __restrict__ x)
{
    int s = blockIdx.x;
    if (s == 0) { if (threadIdx.x == 0) g_rep[0] = 0; return; }
    int ok = 1;
    for (int i = threadIdx.x; i < BN_ * DN_; i += blockDim.x) {
        int b = i >> 6, d = i & 63;
        size_t base = ((size_t)b * SN_ + s) * DN_ + d;
        if (x[base] != x[base - DN_]) ok = 0;
    }
    ok = __syncthreads_and(ok);
    if (threadIdx.x == 0) g_rep[s] = ok;
}

// ---------------------------------------------------------------------------
// Kernel 3: recurrence. __sinf on the serial critical path (25-cyc dep chain
// vs ~60 for the precise poly). Dynamics are contracting (E[log|1+cos|]<0),
// so the ~3e-5 per-step trig error does not accumulate.
// ---------------------------------------------------------------------------
__global__ __launch_bounds__(256) void recur_state(
    const float* __restrict__ omega,
    float* __restrict__ ph_hist, float* __restrict__ wb_hist)
{
    __shared__ int srep[SN_];
    int tid = threadIdx.x;
    for (int i = tid; i < SN_; i += 256) srep[i] = g_rep[i];
    __syncthreads();

    int idx = blockIdx.x * 256 + tid;
    int b = idx >> 7, h = idx & (HN_ - 1);
    float om = omega[h];
    float ph = 0.0f, wb = 0.0f;
    const float* pp = g_pt + (size_t)b * SN_ * HN_ + h;
    float* php = ph_hist + (size_t)b * SN_ * HN_ + h;
    float* wbp = wb_hist + (size_t)b * SN_ * HN_ + h;

    float pnext = pp[0];
    for (int t = 0; t < SN_; t++) {
        float p = pnext;
        if (t < SN_ - 1) pnext = pp[(size_t)(t + 1) * HN_];
        wb += 0.015625f;
        float drive = om + 0.25f * __sinf(wb);   // off the ph-critical path
        ph = ph + drive - __sinf(p - ph);
        if (srep[t]) wb += 0.25f * __sinf(p - wb);
        php[(size_t)t * HN_] = ph;
        wbp[(size_t)t * HN_] = wb;
    }
}

// ---------------------------------------------------------------------------
// Kernel 4: featurize — 2 adjacent h per thread, __half2 stores, fast trig
// feats [M, 7H]: cos ph | sin ph | cos ph/2 | sin ph/2 | cos wb | sin wb | ph
// ---------------------------------------------------------------------------
__global__ __launch_bounds__(256) void featurize(
    const float* __restrict__ ph_hist, const float* __restrict__ wb_hist)
{
    size_t gid = (size_t)blockIdx.x * 256 + threadIdx.x;   // over M*H/2
    size_t m = gid >> 6;
    int h = (int)(gid & 63) * 2;
    float2 ph = *(const float2*)(ph_hist + m * HN_ + h);
    float2 wb = *(const float2*)(wb_hist + m * HN_ + h);
    float c1a, s1a, c2a, s2a, c3a, s3a, c1b, s1b, c2b, s2b, c3b, s3b;
    __sincosf(ph.x, &s1a, &c1a); __sincosf(ph.y, &s1b, &c1b);
    __sincosf(0.5f * ph.x, &s2a, &c2a); __sincosf(0.5f * ph.y, &s2b, &c2b);
    __sincosf(wb.x, &s3a, &c3a); __sincosf(wb.y, &s3b, &c3b);
    __half2* f = (__half2*)(g_f + m * FK_ + h);
    f[0 * HN_ / 2] = __floats2half2_rn(c1a, c1b);
    f[1 * HN_ / 2] = __floats2half2_rn(s1a, s1b);
    f[2 * HN_ / 2] = __floats2half2_rn(c2a, c2b);
    f[3 * HN_ / 2] = __floats2half2_rn(s2a, s2b);
    f[4 * HN_ / 2] = __floats2half2_rn(c3a, c3b);
    f[5 * HN_ / 2] = __floats2half2_rn(s3a, s3b);
    f[6 * HN_ / 2] = __floats2half2_rn(ph.x, ph.y);
}

// ---------------------------------------------------------------------------
// Kernel 5: Wr -> fp16
// ---------------------------------------------------------------------------
__global__ __launch_bounds__(256) void wconv(const float* __restrict__ Wr)
{
    size_t i = (size_t)blockIdx.x * 256 + threadIdx.x;
    if (i < (size_t)ON_ * FK_) g_w[i] = __float2half(Wr[i]);
}

// ---------------------------------------------------------------------------
// Kernel 6: HMMA GEMM  C[m,o] = feats[m,:] . Wr[o,:] + br[o]
// CTA 128x128, K chunks of 64 fp16 (128B SW128 rows).
// 3-stage cp.async pipeline, ONE __syncthreads per chunk (3 stages make the
// stage-(c-1) WAR hazard covered by the top-of-iteration barrier).
// 8 warps: 4 along M x 2 along N; warp tile 32x64 via m16n8k16.
// ---------------------------------------------------------------------------
#define ASZ   16384
#define STAGE 32768
#define GEMM_SMEM (3 * STAGE + 1024)
#define NCHUNK 14

__global__ __launch_bounds__(256, 2) void gemm_hmma(
    const float* __restrict__ br, float* __restrict__ C)
{
    extern __shared__ char smem[];
    uint32_t sb = (smem_u32(smem) + 1023) & ~1023u;
    int tid = threadIdx.x;
    int lane = tid & 31, wid = tid >> 5;
    int warpM = wid & 3, warpN = wid >> 2;
    int bn = blockIdx.x * 128;                 // N tile (0..3)
    size_t bm = (size_t)blockIdx.y * 128;      // M tile

    const __half* Ab = g_f + bm * FK_;
    const __half* Bb = g_w + (size_t)bn * FK_;

    auto load_chunk = [&](int c) {
        uint32_t stb = sb + (c % 3) * STAGE;
        int k0 = c * 64;
#pragma unroll
        for (int u = tid; u < 1024; u += 256) {
            int row = u >> 3, sg = (u & 7) * 16;
            uint32_t off = SWZ(row * 128 + sg);
            cp16(stb + off, (const char*)(Ab + (size_t)row * FK_ + k0) + sg);
            cp16(stb + ASZ + off, (const char*)(Bb + (size_t)row * FK_ + k0) + sg);
        }
    };

    float acc[2][8][4];
#pragma unroll
    for (int mt = 0; mt < 2; mt++)
#pragma unroll
        for (int f = 0; f < 8; f++)
#pragma unroll
            for (int j = 0; j < 4; j++) acc[mt][f][j] = 0.0f;

    int aRow = warpM * 32 + (lane & 15);
    int aK8  = (lane >> 4);
    int bNr  = warpN * 64 + ((lane >> 4) << 3) + (lane & 7);
    int bK8  = (lane >> 3) & 1;

    load_chunk(0); CP_COMMIT();
    load_chunk(1); CP_COMMIT();

    for (int c = 0; c < NCHUNK; c++) {
        if (c + 1 < NCHUNK) { CP_WAIT(1); } else { CP_WAIT(0); }
        __syncthreads();
        uint32_t stb = sb + (c % 3) * STAGE;
#pragma unroll
        for (int kk = 0; kk < 4; kk++) {
            uint32_t a[2][4], b[4][4];
#pragma unroll
            for (int mt = 0; mt < 2; mt++) {
                int khalf = kk * 16 + aK8 * 8;
                ldm4(a[mt], stb + SWZ((aRow + mt * 16) * 128 + khalf * 2));
            }
#pragma unroll
            for (int np = 0; np < 4; np++) {
                int khalf = kk * 16 + bK8 * 8;
                ldm4(b[np], stb + ASZ + SWZ((bNr + np * 16) * 128 + khalf * 2));
            }
#pragma unroll
            for (int mt = 0; mt < 2; mt++)
#pragma unroll
                for (int np = 0; np < 4; np++) {
                    mma16816(acc[mt][np * 2 + 0], a[mt], &b[np][0]);
                    mma16816(acc[mt][np * 2 + 1], a[mt], &b[np][2]);
                }
        }
        if (c + 2 < NCHUNK) { load_chunk(c + 2); CP_COMMIT(); }
    }

    // epilogue
    int g = lane >> 2, t = lane & 3;
#pragma unroll
    for (int f = 0; f < 8; f++) {
        int col = bn + warpN * 64 + f * 8 + 2 * t;
        float2 bv = *(const float2*)(br + col);
#pragma unroll
        for (int mt = 0; mt < 2; mt++) {
            int r0 = warpM * 32 + mt * 16 + g;
            float* c0 = C + (bm + r0) * (size_t)ON_ + col;
            float* c1 = C + (bm + r0 + 8) * (size_t)ON_ + col;
            float2 v0 = { acc[mt][f][0] + bv.x, acc[mt][f][1] + bv.y };
            float2 v1 = { acc[mt][f][2] + bv.x, acc[mt][f][3] + bv.y };
            *(float2*)c0 = v0;
            *(float2*)c1 = v1;
        }
    }
}

// ---------------------------------------------------------------------------
extern "C" void kernel_launch(void* const* d_in, const int* in_sizes, int n_in,
                              void* d_out, int out_size)
{
    const float* x     = (const float*)d_in[0];
    const float* We    = (const float*)d_in[1];
    const float* be    = (const float*)d_in[2];
    const float* omega = (const float*)d_in[3];
    const float* Wr    = (const float*)d_in[4];
    const float* br    = (const float*)d_in[5];

    float* out     = (float*)d_out;
    float* logits  = out;                                   // [B,S,O]
    float* ph_hist = out + (size_t)MTOT_ * ON_;             // [B,S,H]
    float* wb_hist = ph_hist + (size_t)MTOT_ * HN_;         // [B,S,H]

    cudaFuncSetAttribute(gemm_hmma, cudaFuncAttributeMaxDynamicSharedMemorySize, GEMM_SMEM);

    encoder_kernel<<<BN_ * (SN_ / 8), 128>>>(x, We, be);
    rep_kernel<<<SN_, 256>>>(x);
    recur_state<<<(BN_ * HN_) / 256, 256>>>(omega, ph_hist, wb_hist);
    featurize<<<(MTOT_ * HN_ / 2) / 256, 256>>>(ph_hist, wb_hist);
    wconv<<<(ON_ * FK_ + 255) / 256, 256>>>(Wr);
    gemm_hmma<<<dim3(4, 1024), 256, GEMM_SMEM>>>(br, logits);
}